// round 11
// baseline (speedup 1.0000x reference)
#include <cuda_runtime.h>
#include <math.h>
#include <stdint.h>

#define D_HALF   512
#define NPOS     8192
#define SPINE_N  10
#define MAX_TOK  131072
#define NCHAIN   8           // independent chains per position (one per warp)

__constant__ int c_spine[SPINE_N] = {0, 2, 4, 12, 36, 104, 304, 888, 2592, 7568};

// Per-position token linked lists, 8 chains each (device globals: no alloc).
__device__ int g_head[NPOS * NCHAIN];   // memset to -1 each call
__device__ int g_next[MAX_TOK];

// Single pass: push each token onto chain (tok & 7) of its position.
__global__ void __launch_bounds__(256) build_kernel(
    const int* __restrict__ positions, int ntok)
{
    const int i = blockIdx.x * blockDim.x + threadIdx.x;
    if (i < ntok) {
        const int pos = positions[i];
        g_next[i] = atomicExch(&g_head[pos * NCHAIN + (i & (NCHAIN - 1))], i);
    }
}

// One block (256 thr / 8 warps) per position: build the 4 KB concat row once
// in shared memory; each WARP independently walks its own chain and streams
// full rows — 8 concurrent write streams per block.
__global__ void __launch_bounds__(256) gather_kernel(
    const float2* __restrict__ pe2,    // [NPOS, 256] float2
    const float*  __restrict__ W1,     // [512, 3] row-major
    const float*  __restrict__ b1,
    const float*  __restrict__ gamma,
    const float*  __restrict__ beta,
    float4*       __restrict__ out4)   // [ntok, 256] float4
{
    __shared__ alignas(128) float2 srow[512];  // 4 KB: [0,256)=pe, [256,512)=lat
    __shared__ float sred[8];
    __shared__ int   sheads[NCHAIN];

    const int pos  = blockIdx.x;
    const int tid  = threadIdx.x;      // 256 threads, dims 2*tid, 2*tid+1
    const int wid  = tid >> 5;
    const int lane = tid & 31;

    if (tid < NCHAIN) sheads[tid] = g_head[pos * NCHAIN + tid];

    // --- lattice features (scalar, per block) ---
    int level = 0;
#pragma unroll
    for (int i = 0; i < SPINE_N; i++) level += (c_spine[i] <= pos) ? 1 : 0;
    const float left  = (float)(pos - c_spine[level - 1]);
    const float right = (level < SPINE_N) ? (float)(c_spine[level] - pos) : 0.0f;
    const float lv    = (float)level;

    // --- h = feats @ W1^T + b1, dims 2*tid, 2*tid+1 ---
    float h[2];
    float lsum = 0.0f;
#pragma unroll
    for (int k = 0; k < 2; k++) {
        const int d = 2 * tid + k;
        h[k] = fmaf(__ldg(&W1[d * 3 + 0]), left,
               fmaf(__ldg(&W1[d * 3 + 1]), right,
               fmaf(__ldg(&W1[d * 3 + 2]), lv, __ldg(&b1[d]))));
        lsum += h[k];
    }

    // --- block LayerNorm (mean, then two-pass variance) ---
#pragma unroll
    for (int o = 16; o > 0; o >>= 1) lsum += __shfl_xor_sync(0xffffffffu, lsum, o);
    if (lane == 0) sred[wid] = lsum;
    __syncthreads();
    float mu = 0.0f;
#pragma unroll
    for (int w = 0; w < 8; w++) mu += sred[w];
    mu *= (1.0f / (float)D_HALF);

    float vs = 0.0f;
#pragma unroll
    for (int k = 0; k < 2; k++) { const float dd = h[k] - mu; vs = fmaf(dd, dd, vs); }
    __syncthreads();
#pragma unroll
    for (int o = 16; o > 0; o >>= 1) vs += __shfl_xor_sync(0xffffffffu, vs, o);
    if (lane == 0) sred[wid] = vs;
    __syncthreads();
    float var = 0.0f;
#pragma unroll
    for (int w = 0; w < 8; w++) var += sred[w];
    const float rstd = rsqrtf(var * (1.0f / (float)D_HALF) + 1e-5f);

    // --- gamma/beta + exact-erf GELU -> smem lat half (float2 per thread) ---
    {
        float g[2];
#pragma unroll
        for (int k = 0; k < 2; k++) {
            const int d = 2 * tid + k;
            const float x = fmaf((h[k] - mu) * rstd, __ldg(&gamma[d]), __ldg(&beta[d]));
            g[k] = 0.5f * x * (1.0f + erff(x * 0.70710678118654752440f));
        }
        srow[256 + tid] = make_float2(g[0], g[1]);
    }

    // --- pe row (read once per position) -> smem pe half ---
    srow[tid] = __ldg(&pe2[(size_t)pos * 256 + tid]);

    __syncthreads();  // smem row complete

    // --- each warp walks its own chain, streaming full 4 KB rows ---
    // Lane l covers row float4 elements l, l+32, ..., l+224 (128 B).
    const float4* s4 = (const float4*)srow;
    float4 v[8];
#pragma unroll
    for (int k = 0; k < 8; k++) v[k] = s4[lane + 32 * k];

    int tok = sheads[wid];
    while (tok >= 0) {
        const int nxt = __ldg(&g_next[tok]);   // L2 hit; overlaps stores below
        float4* __restrict__ dst = out4 + (size_t)tok * 256;
#pragma unroll
        for (int k = 0; k < 8; k++) dst[lane + 32 * k] = v[k];
        tok = nxt;
    }
}

extern "C" void kernel_launch(void* const* d_in, const int* in_sizes, int n_in,
                              void* d_out, int out_size)
{
    const int*   positions = (const int*)  d_in[0];
    const float* pe        = (const float*)d_in[1];
    const float* W1        = (const float*)d_in[2];
    const float* b1        = (const float*)d_in[3];
    const float* ln_gamma  = (const float*)d_in[4];
    const float* ln_beta   = (const float*)d_in[5];
    float* out = (float*)d_out;

    const int ntok = in_sizes[0];  // B*S = 131072

    void* head_ptr = nullptr;
    cudaGetSymbolAddress(&head_ptr, g_head);
    cudaMemsetAsync(head_ptr, 0xFF, NPOS * NCHAIN * sizeof(int));  // heads = -1

    build_kernel<<<(ntok + 255) / 256, 256>>>(positions, ntok);

    gather_kernel<<<NPOS, 256>>>((const float2*)pe, W1, b1, ln_gamma, ln_beta,
                                 (float4*)out);
}

// round 14
// speedup vs baseline: 1.0048x; 1.0048x over previous
#include <cuda_runtime.h>
#include <math.h>
#include <stdint.h>

#define D_HALF   512
#define NPOS     8192
#define SPINE_N  10
#define MAX_TOK  131072
#define NCHAIN   4           // independent chains per position (one per warp)

__constant__ int c_spine[SPINE_N] = {0, 2, 4, 12, 36, 104, 304, 888, 2592, 7568};

// Per-position token linked lists, 4 chains each. Encoding: value = tok+1,
// 0 = empty. Zero-initialized .bss is a valid empty state (first call), and
// gather_kernel self-cleans heads back to 0 for subsequent calls/replays.
__device__ int g_head[NPOS * NCHAIN];
__device__ int g_next[MAX_TOK];

// Single pass: push each token onto chain (tok & 3) of its position.
__global__ void __launch_bounds__(256) build_kernel(
    const int* __restrict__ positions, int ntok)
{
    const int i = blockIdx.x * blockDim.x + threadIdx.x;
    if (i < ntok) {
        const int pos = positions[i];
        g_next[i] = atomicExch(&g_head[pos * NCHAIN + (i & (NCHAIN - 1))], i + 1);
    }
}

// One block per position. Prologue (row construction) has NO dependence on
// build_kernel; only the chain walk does. With PDL, this kernel launches
// while build_kernel is still running and griddepcontrol.wait gates only the
// head reads — the prep pass vanishes from the critical path.
__global__ void __launch_bounds__(128) gather_kernel(
    const float4* __restrict__ pe4,    // [NPOS, 128] float4
    const float*  __restrict__ W1,     // [512, 3] row-major
    const float*  __restrict__ b1,
    const float*  __restrict__ gamma,
    const float*  __restrict__ beta,
    float4*       __restrict__ out4)   // [ntok, 256] float4
{
    __shared__ alignas(128) float4 srow[256];  // 4 KB: [0,128)=pe, [128,256)=lat
    __shared__ float sred[4];
    __shared__ int   sheads[NCHAIN];

    const int pos  = blockIdx.x;
    const int tid  = threadIdx.x;      // 128 threads, dims 4*tid..4*tid+3
    const int wid  = tid >> 5;
    const int lane = tid & 31;

    // ---------------- prologue: build the 4 KB row (independent of build) ---
    int level = 0;
#pragma unroll
    for (int i = 0; i < SPINE_N; i++) level += (c_spine[i] <= pos) ? 1 : 0;
    const float left  = (float)(pos - c_spine[level - 1]);
    const float right = (level < SPINE_N) ? (float)(c_spine[level] - pos) : 0.0f;
    const float lv    = (float)level;

    float h[4];
    float lsum = 0.0f;
#pragma unroll
    for (int k = 0; k < 4; k++) {
        const int d = 4 * tid + k;
        h[k] = fmaf(__ldg(&W1[d * 3 + 0]), left,
               fmaf(__ldg(&W1[d * 3 + 1]), right,
               fmaf(__ldg(&W1[d * 3 + 2]), lv, __ldg(&b1[d]))));
        lsum += h[k];
    }

#pragma unroll
    for (int o = 16; o > 0; o >>= 1) lsum += __shfl_xor_sync(0xffffffffu, lsum, o);
    if (lane == 0) sred[wid] = lsum;
    __syncthreads();
    const float mu = (sred[0] + sred[1] + sred[2] + sred[3]) * (1.0f / (float)D_HALF);

    float vs = 0.0f;
#pragma unroll
    for (int k = 0; k < 4; k++) { const float dd = h[k] - mu; vs = fmaf(dd, dd, vs); }
    __syncthreads();
#pragma unroll
    for (int o = 16; o > 0; o >>= 1) vs += __shfl_xor_sync(0xffffffffu, vs, o);
    if (lane == 0) sred[wid] = vs;
    __syncthreads();
    const float rstd = rsqrtf((sred[0] + sred[1] + sred[2] + sred[3]) *
                              (1.0f / (float)D_HALF) + 1e-5f);

    {
        float g[4];
#pragma unroll
        for (int k = 0; k < 4; k++) {
            const int d = 4 * tid + k;
            const float x = fmaf((h[k] - mu) * rstd, __ldg(&gamma[d]), __ldg(&beta[d]));
            g[k] = 0.5f * x * (1.0f + erff(x * 0.70710678118654752440f));
        }
        srow[128 + tid] = make_float4(g[0], g[1], g[2], g[3]);
    }
    srow[tid] = __ldg(&pe4[(size_t)pos * 128 + tid]);

    // ---------------- wait for build_kernel (PDL gate), then read heads -----
    asm volatile("griddepcontrol.wait;" ::: "memory");
    if (tid < NCHAIN) {
        const int hv = g_head[pos * NCHAIN + tid];
        sheads[tid] = hv;
        g_head[pos * NCHAIN + tid] = 0;   // self-clean for next call/replay
    }
    __syncthreads();  // srow + sheads visible

    // ---------------- each warp walks its own chain, streaming 4 KB rows ---
    float4 v[8];
#pragma unroll
    for (int k = 0; k < 8; k++) v[k] = srow[lane + 32 * k];

    int t = sheads[wid];
    while (t > 0) {
        const int tok = t - 1;
        const int nxt = __ldg(&g_next[tok]);   // L2 hit; overlaps stores below
        float4* __restrict__ dst = out4 + (size_t)tok * 256;
#pragma unroll
        for (int k = 0; k < 8; k++) __stcs(dst + lane + 32 * k, v[k]);
        t = nxt;
    }
}

extern "C" void kernel_launch(void* const* d_in, const int* in_sizes, int n_in,
                              void* d_out, int out_size)
{
    const int*   positions = (const int*)  d_in[0];
    const float* pe        = (const float*)d_in[1];
    const float* W1        = (const float*)d_in[2];
    const float* b1        = (const float*)d_in[3];
    const float* ln_gamma  = (const float*)d_in[4];
    const float* ln_beta   = (const float*)d_in[5];
    float* out = (float*)d_out;

    const int ntok = in_sizes[0];  // B*S = 131072

    build_kernel<<<(ntok + 255) / 256, 256>>>(positions, ntok);

    // Launch gather with programmatic stream serialization: it starts while
    // build is still in flight; griddepcontrol.wait gates the head reads.
    {
        cudaLaunchConfig_t cfg = {};
        cfg.gridDim  = dim3(NPOS, 1, 1);
        cfg.blockDim = dim3(128, 1, 1);
        cfg.dynamicSmemBytes = 0;
        cudaLaunchAttribute attr[1];
        attr[0].id = cudaLaunchAttributeProgrammaticStreamSerialization;
        attr[0].val.programmaticStreamSerializationAllowed = 1;
        cfg.attrs = attr;
        cfg.numAttrs = 1;
        cudaLaunchKernelEx(&cfg, gather_kernel,
                           (const float4*)pe, W1, b1, ln_gamma, ln_beta,
                           (float4*)out);
    }
}